// round 1
// baseline (speedup 1.0000x reference)
#include <cuda_runtime.h>

// out[b,s,d] = x[b,s,d] + enc(s,d)
//   enc(s,d) = sin(s / 10000^(d/D)) if d even else cos(s / 10000^(d/D))
// Shapes: B=8, S=4096, D=1024, fp32.
//
// Strategy: HBM-bound (1 GiB traffic). One thread owns one (s, d..d+3)
// encoding float4, computes the 4 transcendentals ONCE, and applies them to
// all 8 batch slices (same (s,d) offset, stride S*D). float4 vectorized,
// fully coalesced, MLP=8 per thread.

#define B_ 8
#define S_ 4096
#define D_ 1024
#define SD_ (S_ * D_)           // 4,194,304
#define SD4_ (SD_ / 4)          // 1,048,576 float4 tiles per batch slice

__global__ __launch_bounds__(256) void pe_add_kernel(
    const float4* __restrict__ x, float4* __restrict__ out)
{
    const int idx4 = blockIdx.x * blockDim.x + threadIdx.x;   // [0, SD4_)
    const int dcol4 = idx4 & (D_ / 4 - 1);                    // float4 column in D
    const int s     = idx4 >> 8;                              // D_/4 = 256 → >>8
    const int d0    = dcol4 * 4;

    // Issue all 8 batch loads first (independent of enc compute) → MLP=8.
    float4 v[B_];
#pragma unroll
    for (int b = 0; b < B_; b++)
        v[b] = x[(long long)b * SD4_ + idx4];

    // Compute the encoding float4 once.
    // angle(d) = s * 10000^(-d/D);  even d → sin, odd d → cos
    const float neg_log2_1e4_over_D = -(13.287712379549449f / 1024.0f); // log2(10000)/1024
    const float sf = (float)s;
    float e0, e1, e2, e3;
    {
        float a0 = sf * exp2f((float)(d0 + 0) * neg_log2_1e4_over_D);
        float a1 = sf * exp2f((float)(d0 + 1) * neg_log2_1e4_over_D);
        float a2 = sf * exp2f((float)(d0 + 2) * neg_log2_1e4_over_D);
        float a3 = sf * exp2f((float)(d0 + 3) * neg_log2_1e4_over_D);
        e0 = sinf(a0);   // even
        e1 = cosf(a1);   // odd
        e2 = sinf(a2);   // even
        e3 = cosf(a3);   // odd
    }

#pragma unroll
    for (int b = 0; b < B_; b++) {
        float4 r = v[b];
        r.x += e0; r.y += e1; r.z += e2; r.w += e3;
        out[(long long)b * SD4_ + idx4] = r;
    }
}

extern "C" void kernel_launch(void* const* d_in, const int* in_sizes, int n_in,
                              void* d_out, int out_size)
{
    const float4* x = (const float4*)d_in[0];
    float4* out = (float4*)d_out;
    // SD4_ threads total, 256 per block → 4096 blocks
    pe_add_kernel<<<SD4_ / 256, 256>>>(x, out);
}